// round 12
// baseline (speedup 1.0000x reference)
#include <cuda_runtime.h>

#define EPS 1e-5f
#define C_DIM 64
#define B_DIM 8
#define CTX_DIM 256

// Fused modulation coefficients: [0..511]   = A[b][c] = gamma[c]*(1+scale[b][c])
//                                [512..1023]= B[b][c] = beta[c]*(1+scale[b][c]) + shift[b][c]
__device__ __align__(16) float g_coef[2 * B_DIM * C_DIM];
// g_bound[k] = first row whose batch >= k+1. batch(row) = #{k : bound[k] <= row}
__device__ int g_bound[B_DIM - 1];

// ---------------------------------------------------------------------------
// Setup kernel: blocks 0..63 = tiny MLP (one warp per (batch,channel) pair);
// blocks 64..70 = one block per batch boundary, 257-way block-parallel search.
// Triggers programmatic launch completion at start so norm CTAs can launch.
// ---------------------------------------------------------------------------
__global__ void __launch_bounds__(256)
setup_kernel(const float* __restrict__ token,  // [8,256]
             const float* __restrict__ W,      // [128,256]
             const float* __restrict__ bvec,   // [128]
             const float* __restrict__ gamma,  // [64]
             const float* __restrict__ beta,   // [64]
             const int* __restrict__ coors,    // [N,4] int32, col 0 sorted
             int n_rows)
{
    cudaTriggerProgrammaticLaunchCompletion();

    const int tid  = threadIdx.x;
    const int warp = tid >> 5;
    const int lane = tid & 31;

    if (blockIdx.x < 64) {
        const int wg = blockIdx.x * 8 + warp;   // 0..511
        const int j = wg >> 6;
        const int c = wg & 63;

        const float* trow = token + j * CTX_DIM;
        const float* wsh  = W + c * CTX_DIM;
        const float* wsc  = W + (C_DIM + c) * CTX_DIM;

        float tv[8], wa[8], wb[8];
#pragma unroll
        for (int i = 0; i < 8; ++i) {
            const int k = lane + 32 * i;
            tv[i] = __ldg(trow + k);
            wa[i] = __ldg(wsh + k);
            wb[i] = __ldg(wsc + k);
        }
        float acc_sh = 0.0f, acc_sc = 0.0f;
#pragma unroll
        for (int i = 0; i < 8; ++i) {
            const float s = tv[i] / (1.0f + expf(-tv[i]));
            acc_sh += s * wa[i];
            acc_sc += s * wb[i];
        }
#pragma unroll
        for (int o = 16; o >= 1; o >>= 1) {
            acc_sh += __shfl_xor_sync(0xffffffffu, acc_sh, o);
            acc_sc += __shfl_xor_sync(0xffffffffu, acc_sc, o);
        }
        if (lane == 0) {
            const float shift = acc_sh + bvec[c];
            const float scale = acc_sc + bvec[C_DIM + c];
            g_coef[j * C_DIM + c]                 = gamma[c] * (1.0f + scale);
            g_coef[B_DIM * C_DIM + j * C_DIM + c] = beta[c] * (1.0f + scale) + shift;
        }
    } else {
        __shared__ int s_lo, s_hi;
        const int k = (int)blockIdx.x - 63;      // 1..7
        if (tid == 0) { s_lo = 0; s_hi = n_rows; }
        __syncthreads();

        while (s_hi - s_lo > 256) {
            const int lo = s_lo, hi = s_hi;
            const long long len = hi - lo;
            const int pos = lo + (int)(((long long)(tid + 1) * len) / 257);
            const bool ge = __ldg(coors + (long long)pos * 4) >= k;
            const int posL = lo + (int)(((long long)tid * len) / 257);
            const bool geL = (tid == 0) ? false
                                        : (__ldg(coors + (long long)posL * 4) >= k);
            __syncthreads();
            if (ge && !geL) {
                s_lo = (tid == 0) ? lo : posL;
                s_hi = pos;
            }
            if (tid == 255 && !ge) s_lo = pos;
            __syncthreads();
        }
        __shared__ int s_ans;
        if (tid == 0) s_ans = s_hi;
        __syncthreads();
        const int lo = s_lo, hi = s_hi;
        const int pos = lo + tid;
        if (pos < hi && __ldg(coors + (long long)pos * 4) >= k) {
            atomicMin(&s_ans, pos);
        }
        __syncthreads();
        if (tid == 0) g_bound[k - 1] = s_ans;
    }
}

// ---------------------------------------------------------------------------
// Norm kernel: 4 lanes per row, 4 float4 per lane (one full row per thread
// group of 4), ONE row per thread. Warp covers 8 rows; block covers 64 rows.
// Only 2 shuffle rounds (4 SHFLs/thread). PDL wait at top.
// ---------------------------------------------------------------------------
template <bool GUARD>
__global__ void __launch_bounds__(256)
norm_mod_kernel(const float* __restrict__ x,
                float* __restrict__ out,
                int n_rows)
{
    __shared__ float sA[B_DIM * C_DIM];
    __shared__ float sB[B_DIM * C_DIM];
    __shared__ int sbnd[B_DIM - 1];

    cudaGridDependencySynchronize();

    const int tid = threadIdx.x;
    for (int i = tid; i < B_DIM * C_DIM; i += 256) {
        sA[i] = g_coef[i];
        sB[i] = g_coef[B_DIM * C_DIM + i];
    }
    if (tid < B_DIM - 1) sbnd[tid] = g_bound[tid];
    __syncthreads();

    int bnd[B_DIM - 1];
#pragma unroll
    for (int k = 0; k < B_DIM - 1; ++k) bnd[k] = sbnd[k];

    const int warp = tid >> 5;
    const int lane = tid & 31;
    const int g    = lane >> 2;   // row slot 0..7 within warp
    const int sub  = lane & 3;    // lane within row (4 lanes x 4 float4)

    const int row = blockIdx.x * 64 + warp * 8 + g;
    if (GUARD && row >= n_rows) return;

    const float4* p = reinterpret_cast<const float4*>(x) + (long long)row * 16;
    float4 v0 = __ldcs(p + sub);
    float4 v1 = __ldcs(p + sub + 4);
    float4 v2 = __ldcs(p + sub + 8);
    float4 v3 = __ldcs(p + sub + 12);

    float s = ((v0.x + v0.y) + (v0.z + v0.w)) + ((v1.x + v1.y) + (v1.z + v1.w))
            + ((v2.x + v2.y) + (v2.z + v2.w)) + ((v3.x + v3.y) + (v3.z + v3.w));
    float s2 = v0.x * v0.x + v0.y * v0.y + v0.z * v0.z + v0.w * v0.w
             + v1.x * v1.x + v1.y * v1.y + v1.z * v1.z + v1.w * v1.w
             + v2.x * v2.x + v2.y * v2.y + v2.z * v2.z + v2.w * v2.w
             + v3.x * v3.x + v3.y * v3.y + v3.z * v3.z + v3.w * v3.w;

#pragma unroll
    for (int o = 2; o >= 1; o >>= 1) {
        s  += __shfl_xor_sync(0xffffffffu, s,  o);
        s2 += __shfl_xor_sync(0xffffffffu, s2, o);
    }

    const float mu  = s * (1.0f / 64.0f);
    const float var = s2 * (1.0f / 64.0f) - mu * mu;
    const float rs  = rsqrtf(var + EPS);

    int b = 0;
#pragma unroll
    for (int k = 0; k < B_DIM - 1; ++k) b += (row >= bnd[k]);

    const float4* ap = reinterpret_cast<const float4*>(sA + b * C_DIM);
    const float4* bp = reinterpret_cast<const float4*>(sB + b * C_DIM);
    float4* po = reinterpret_cast<float4*>(out) + (long long)row * 16;

    {
        const float4 a = ap[sub], bb = bp[sub];
        float4 o4;
        o4.x = (v0.x - mu) * rs * a.x + bb.x;
        o4.y = (v0.y - mu) * rs * a.y + bb.y;
        o4.z = (v0.z - mu) * rs * a.z + bb.z;
        o4.w = (v0.w - mu) * rs * a.w + bb.w;
        __stcs(po + sub, o4);
    }
    {
        const float4 a = ap[sub + 4], bb = bp[sub + 4];
        float4 o4;
        o4.x = (v1.x - mu) * rs * a.x + bb.x;
        o4.y = (v1.y - mu) * rs * a.y + bb.y;
        o4.z = (v1.z - mu) * rs * a.z + bb.z;
        o4.w = (v1.w - mu) * rs * a.w + bb.w;
        __stcs(po + sub + 4, o4);
    }
    {
        const float4 a = ap[sub + 8], bb = bp[sub + 8];
        float4 o4;
        o4.x = (v2.x - mu) * rs * a.x + bb.x;
        o4.y = (v2.y - mu) * rs * a.y + bb.y;
        o4.z = (v2.z - mu) * rs * a.z + bb.z;
        o4.w = (v2.w - mu) * rs * a.w + bb.w;
        __stcs(po + sub + 8, o4);
    }
    {
        const float4 a = ap[sub + 12], bb = bp[sub + 12];
        float4 o4;
        o4.x = (v3.x - mu) * rs * a.x + bb.x;
        o4.y = (v3.y - mu) * rs * a.y + bb.y;
        o4.z = (v3.z - mu) * rs * a.z + bb.z;
        o4.w = (v3.w - mu) * rs * a.w + bb.w;
        __stcs(po + sub + 12, o4);
    }
}

// ---------------------------------------------------------------------------
// Launch. Inputs (metadata order): x, dataset_token, gamma, beta, W, b, coors
// Norm kernel launched with Programmatic Stream Serialization (PDL).
// ---------------------------------------------------------------------------
extern "C" void kernel_launch(void* const* d_in, const int* in_sizes, int n_in,
                              void* d_out, int out_size)
{
    const float* x      = (const float*)d_in[0];
    const float* token  = (const float*)d_in[1];
    const float* gamma  = (const float*)d_in[2];
    const float* beta   = (const float*)d_in[3];
    const float* W      = (const float*)d_in[4];
    const float* bvec   = (const float*)d_in[5];
    const int*   coors  = (const int*)d_in[6];
    float* out = (float*)d_out;

    const int n_rows = in_sizes[0] / C_DIM;
    const int grid = (n_rows + 63) / 64;

    setup_kernel<<<64 + (B_DIM - 1), 256>>>(token, W, bvec, gamma, beta, coors, n_rows);

    cudaLaunchConfig_t cfg = {};
    cfg.gridDim = dim3((unsigned)grid, 1, 1);
    cfg.blockDim = dim3(256, 1, 1);
    cfg.dynamicSmemBytes = 0;
    cfg.stream = 0;
    cudaLaunchAttribute attrs[1];
    attrs[0].id = cudaLaunchAttributeProgrammaticStreamSerialization;
    attrs[0].val.programmaticStreamSerializationAllowed = 1;
    cfg.attrs = attrs;
    cfg.numAttrs = 1;

    if (n_rows % 64 == 0) {
        cudaLaunchKernelEx(&cfg, norm_mod_kernel<false>, x, out, n_rows);
    } else {
        cudaLaunchKernelEx(&cfg, norm_mod_kernel<true>, x, out, n_rows);
    }
}